// round 1
// baseline (speedup 1.0000x reference)
#include <cuda_runtime.h>

#define NN 30000
#define EE 600000
#define HH 128
#define LL 4
#define GG 64
#define TE 64   // edges (or nodes) per block tile

// -------- scratch (static device globals; no allocation allowed) ----------
__device__ float g_h[NN * HH];      // node features
__device__ float g_aggr[NN * HH];   // scatter-add accumulator
__device__ float g_dist[EE];        // per-edge squared distance
__device__ float g_pool[GG * HH];   // per-graph pooled features
__device__ int   g_is64;            // 1 if edge_index/batch are int64

__device__ __forceinline__ int ld_idx(const void* p, long long i, int is64) {
    if (is64) return (int)((const long long*)p)[i];
    return ((const int*)p)[i];
}

__device__ __forceinline__ float silu_f(float v) {
    // v * sigmoid(v) = v / (1 + e^-v); __expf rel err ~2^-21, fine for 1e-3
    return v / (1.0f + __expf(-v));
}

// Detect int32 vs int64 index dtype: for positive indices < 2^31 stored as
// int64, every odd 32-bit word is 0. For random int32 indices in [0,30000),
// 2048 odd-word samples are all zero with probability ~0.
__global__ void detect_kernel(const int* w) {
    __shared__ int nz;
    if (threadIdx.x == 0) nz = 0;
    __syncthreads();
    int f = 0;
    for (int i = threadIdx.x * 2 + 1; i < 4096; i += 2 * 256)
        if (w[i] != 0) f = 1;
    if (f) atomicOr(&nz, 1);
    __syncthreads();
    if (threadIdx.x == 0) g_is64 = (nz == 0) ? 1 : 0;
}

__global__ void embed_kernel(const float* __restrict__ x,
                             const float* __restrict__ w,
                             const float* __restrict__ b) {
    int idx = blockIdx.x * blockDim.x + threadIdx.x;
    if (idx >= NN * HH) return;
    int n = idx >> 7, k = idx & 127;
    g_h[idx] = x[n] * w[k] + b[k];
}

__global__ void dist_kernel(const float* __restrict__ pos, const void* ei) {
    int e = blockIdx.x * blockDim.x + threadIdx.x;
    if (e >= EE) return;
    int is64 = g_is64;
    int r = ld_idx(ei, e, is64);
    int c = ld_idx(ei, (long long)EE + e, is64);
    float dx = pos[3 * r + 0] - pos[3 * c + 0];
    float dy = pos[3 * r + 1] - pos[3 * c + 1];
    float dz = pos[3 * r + 2] - pos[3 * c + 2];
    g_dist[e] = dx * dx + dy * dy + dz * dz;
}

__global__ void zero_aggr_kernel() {
    int idx = blockIdx.x * blockDim.x + threadIdx.x;
    if (idx < NN * HH) g_aggr[idx] = 0.0f;
}

__global__ void zero_pool_kernel() {
    int idx = blockIdx.x * blockDim.x + threadIdx.x;
    if (idx < GG * HH) g_pool[idx] = 0.0f;
}

// ---------------------------------------------------------------------------
// Edge kernel: per 64-edge tile
//   A[e] = [ h[col[e]] (128) | h[row[e]] (128) | dist[e] ]   (257 cols)
//   Hd = silu(A @ W1 + b1)        (64 x 128)
//   m  = Hd @ W2 + b2             (64 x 128)
//   atomicAdd into g_aggr[col[e]]
// 256 threads; per-thread micro-tile 8 edges x 4 cols (32 accumulators).
// ---------------------------------------------------------------------------
__global__ __launch_bounds__(256, 2) void edge_kernel(
    const void* ei,
    const float* __restrict__ W1, const float* __restrict__ B1,
    const float* __restrict__ W2, const float* __restrict__ B2) {
    extern __shared__ float sm[];
    float* A  = sm;                 // TE * 260 (257 used, padded)
    float* Hd = A + TE * 260;       // TE * 128
    float* Ws = Hd + TE * HH;       // 32 * 128
    int* sRow = (int*)(Ws + 32 * HH);
    int* sCol = sRow + TE;

    const int tid = threadIdx.x, tx = tid & 31, ty = tid >> 5;
    const int e0 = blockIdx.x * TE;
    const int is64 = g_is64;

    if (tid < TE) {
        sRow[tid] = ld_idx(ei, e0 + tid, is64);
        sCol[tid] = ld_idx(ei, (long long)EE + e0 + tid, is64);
    }
    __syncthreads();

    // gather x_i = h[col], x_j = h[row]
    for (int idx = tid; idx < TE * 32; idx += 256) {
        int le = idx >> 5, q = idx & 31;
        const float4* src_i = (const float4*)(g_h + (size_t)sCol[le] * HH);
        const float4* src_j = (const float4*)(g_h + (size_t)sRow[le] * HH);
        *(float4*)(A + le * 260 + q * 4)       = src_i[q];
        *(float4*)(A + le * 260 + 128 + q * 4) = src_j[q];
    }
    if (tid < TE) A[tid * 260 + 256] = g_dist[e0 + tid];
    __syncthreads();

    float acc[8][4];
#pragma unroll
    for (int i = 0; i < 8; i++) {
#pragma unroll
        for (int j = 0; j < 4; j++) acc[i][j] = 0.0f;
    }

    // phase 1: A(64x257) @ W1(257x128)
    for (int k0 = 0; k0 < 257; k0 += 32) {
        int nk = min(32, 257 - k0);
        __syncthreads();
        for (int idx = tid; idx < nk * HH; idx += 256)
            Ws[idx] = W1[(k0 + (idx >> 7)) * HH + (idx & 127)];
        __syncthreads();
        for (int kk = 0; kk < nk; kk++) {
            float w0 = Ws[kk * HH + tx];
            float w1 = Ws[kk * HH + tx + 32];
            float w2 = Ws[kk * HH + tx + 64];
            float w3 = Ws[kk * HH + tx + 96];
#pragma unroll
            for (int i = 0; i < 8; i++) {
                float a = A[(ty * 8 + i) * 260 + k0 + kk];
                acc[i][0] += a * w0;
                acc[i][1] += a * w1;
                acc[i][2] += a * w2;
                acc[i][3] += a * w3;
            }
        }
    }

    // bias + silu -> Hd
    {
        float b0 = B1[tx], b1 = B1[tx + 32], b2 = B1[tx + 64], b3 = B1[tx + 96];
#pragma unroll
        for (int i = 0; i < 8; i++) {
            int le = ty * 8 + i;
            Hd[le * HH + tx]      = silu_f(acc[i][0] + b0);
            Hd[le * HH + tx + 32] = silu_f(acc[i][1] + b1);
            Hd[le * HH + tx + 64] = silu_f(acc[i][2] + b2);
            Hd[le * HH + tx + 96] = silu_f(acc[i][3] + b3);
        }
    }

#pragma unroll
    for (int i = 0; i < 8; i++) {
#pragma unroll
        for (int j = 0; j < 4; j++) acc[i][j] = 0.0f;
    }

    // phase 2: Hd(64x128) @ W2(128x128)
    for (int k0 = 0; k0 < 128; k0 += 32) {
        __syncthreads();
        for (int idx = tid; idx < 32 * HH; idx += 256)
            Ws[idx] = W2[(k0 + (idx >> 7)) * HH + (idx & 127)];
        __syncthreads();
        for (int kk = 0; kk < 32; kk++) {
            float w0 = Ws[kk * HH + tx];
            float w1 = Ws[kk * HH + tx + 32];
            float w2 = Ws[kk * HH + tx + 64];
            float w3 = Ws[kk * HH + tx + 96];
#pragma unroll
            for (int i = 0; i < 8; i++) {
                float a = Hd[(ty * 8 + i) * HH + k0 + kk];
                acc[i][0] += a * w0;
                acc[i][1] += a * w1;
                acc[i][2] += a * w2;
                acc[i][3] += a * w3;
            }
        }
    }

    // bias + scatter-add to targets
    {
        float b0 = B2[tx], b1 = B2[tx + 32], b2 = B2[tx + 64], b3 = B2[tx + 96];
#pragma unroll
        for (int i = 0; i < 8; i++) {
            int le = ty * 8 + i;
            float* dst = g_aggr + (size_t)sCol[le] * HH;
            atomicAdd(dst + tx,      acc[i][0] + b0);
            atomicAdd(dst + tx + 32, acc[i][1] + b1);
            atomicAdd(dst + tx + 64, acc[i][2] + b2);
            atomicAdd(dst + tx + 96, acc[i][3] + b3);
        }
    }
}

// ---------------------------------------------------------------------------
// Node kernel: per 64-node tile
//   A[n] = [ h[n] | aggr[n] ]  (256 cols)
//   h[n] = silu(A @ W1 + b1) @ W2 + b2   (in-place update, block-local rows)
// ---------------------------------------------------------------------------
__global__ __launch_bounds__(256, 2) void node_kernel(
    const float* __restrict__ W1, const float* __restrict__ B1,
    const float* __restrict__ W2, const float* __restrict__ B2) {
    extern __shared__ float sm[];
    float* A  = sm;                 // TE * 260 (256 used)
    float* Hd = A + TE * 260;
    float* Ws = Hd + TE * HH;

    const int tid = threadIdx.x, tx = tid & 31, ty = tid >> 5;
    const int n0 = blockIdx.x * TE;

    for (int idx = tid; idx < TE * 32; idx += 256) {
        int ln = idx >> 5, q = idx & 31;
        int n = n0 + ln;
        if (n < NN) {
            *(float4*)(A + ln * 260 + q * 4)       = ((const float4*)(g_h + (size_t)n * HH))[q];
            *(float4*)(A + ln * 260 + 128 + q * 4) = ((const float4*)(g_aggr + (size_t)n * HH))[q];
        }
    }
    __syncthreads();

    float acc[8][4];
#pragma unroll
    for (int i = 0; i < 8; i++) {
#pragma unroll
        for (int j = 0; j < 4; j++) acc[i][j] = 0.0f;
    }

    for (int k0 = 0; k0 < 256; k0 += 32) {
        __syncthreads();
        for (int idx = tid; idx < 32 * HH; idx += 256)
            Ws[idx] = W1[(k0 + (idx >> 7)) * HH + (idx & 127)];
        __syncthreads();
        for (int kk = 0; kk < 32; kk++) {
            float w0 = Ws[kk * HH + tx];
            float w1 = Ws[kk * HH + tx + 32];
            float w2 = Ws[kk * HH + tx + 64];
            float w3 = Ws[kk * HH + tx + 96];
#pragma unroll
            for (int i = 0; i < 8; i++) {
                float a = A[(ty * 8 + i) * 260 + k0 + kk];
                acc[i][0] += a * w0;
                acc[i][1] += a * w1;
                acc[i][2] += a * w2;
                acc[i][3] += a * w3;
            }
        }
    }

    {
        float b0 = B1[tx], b1 = B1[tx + 32], b2 = B1[tx + 64], b3 = B1[tx + 96];
#pragma unroll
        for (int i = 0; i < 8; i++) {
            int le = ty * 8 + i;
            Hd[le * HH + tx]      = silu_f(acc[i][0] + b0);
            Hd[le * HH + tx + 32] = silu_f(acc[i][1] + b1);
            Hd[le * HH + tx + 64] = silu_f(acc[i][2] + b2);
            Hd[le * HH + tx + 96] = silu_f(acc[i][3] + b3);
        }
    }

#pragma unroll
    for (int i = 0; i < 8; i++) {
#pragma unroll
        for (int j = 0; j < 4; j++) acc[i][j] = 0.0f;
    }

    for (int k0 = 0; k0 < 128; k0 += 32) {
        __syncthreads();
        for (int idx = tid; idx < 32 * HH; idx += 256)
            Ws[idx] = W2[(k0 + (idx >> 7)) * HH + (idx & 127)];
        __syncthreads();
        for (int kk = 0; kk < 32; kk++) {
            float w0 = Ws[kk * HH + tx];
            float w1 = Ws[kk * HH + tx + 32];
            float w2 = Ws[kk * HH + tx + 64];
            float w3 = Ws[kk * HH + tx + 96];
#pragma unroll
            for (int i = 0; i < 8; i++) {
                float a = Hd[(ty * 8 + i) * HH + k0 + kk];
                acc[i][0] += a * w0;
                acc[i][1] += a * w1;
                acc[i][2] += a * w2;
                acc[i][3] += a * w3;
            }
        }
    }

    {
        float b0 = B2[tx], b1 = B2[tx + 32], b2 = B2[tx + 64], b3 = B2[tx + 96];
#pragma unroll
        for (int i = 0; i < 8; i++) {
            int ln = ty * 8 + i;
            int n = n0 + ln;
            if (n < NN) {
                float* dst = g_h + (size_t)n * HH;
                dst[tx]      = acc[i][0] + b0;
                dst[tx + 32] = acc[i][1] + b1;
                dst[tx + 64] = acc[i][2] + b2;
                dst[tx + 96] = acc[i][3] + b3;
            }
        }
    }
}

__global__ void pool_kernel(const void* batch) {
    int idx = blockIdx.x * blockDim.x + threadIdx.x;
    if (idx >= NN * 32) return;
    int n = idx >> 5, q = idx & 31;
    int b = ld_idx(batch, n, g_is64);
    float4 v = ((const float4*)(g_h + (size_t)n * HH))[q];
    float* dst = &g_pool[b * HH + q * 4];
    atomicAdd(dst + 0, v.x);
    atomicAdd(dst + 1, v.y);
    atomicAdd(dst + 2, v.z);
    atomicAdd(dst + 3, v.w);
}

__global__ void out_kernel(const float* __restrict__ w1, const float* __restrict__ b1,
                           const float* __restrict__ w2, const float* __restrict__ b2,
                           float* __restrict__ out) {
    int gi = blockIdx.x;
    int j = threadIdx.x;  // 0..31
    float s = b1[j];
    for (int k = 0; k < HH; k++)
        s += g_pool[gi * HH + k] * w1[k * 32 + j];
    float v = silu_f(s) * w2[j];
#pragma unroll
    for (int o = 16; o > 0; o >>= 1)
        v += __shfl_down_sync(0xFFFFFFFFu, v, o);
    if (j == 0) out[gi] = v + b2[0];
}

extern "C" void kernel_launch(void* const* d_in, const int* in_sizes, int n_in,
                              void* d_out, int out_size) {
    const float* x       = (const float*)d_in[0];
    const float* pos     = (const float*)d_in[1];
    const void*  ei      = d_in[2];
    const void*  batch   = d_in[3];
    const float* emb_w   = (const float*)d_in[4];
    const float* emb_b   = (const float*)d_in[5];
    const float* msg_w1  = (const float*)d_in[6];
    const float* msg_b1  = (const float*)d_in[7];
    const float* msg_w2  = (const float*)d_in[8];
    const float* msg_b2  = (const float*)d_in[9];
    const float* node_w1 = (const float*)d_in[10];
    const float* node_b1 = (const float*)d_in[11];
    const float* node_w2 = (const float*)d_in[12];
    const float* node_b2 = (const float*)d_in[13];
    const float* out_w1  = (const float*)d_in[14];
    const float* out_b1  = (const float*)d_in[15];
    const float* out_w2  = (const float*)d_in[16];
    const float* out_b2  = (const float*)d_in[17];

    size_t smem = (size_t)(TE * 260 + TE * HH + 32 * HH) * sizeof(float)
                + 2 * TE * sizeof(int);
    cudaFuncSetAttribute(edge_kernel, cudaFuncAttributeMaxDynamicSharedMemorySize, (int)smem);
    cudaFuncSetAttribute(node_kernel, cudaFuncAttributeMaxDynamicSharedMemorySize, (int)smem);

    detect_kernel<<<1, 256>>>((const int*)ei);
    embed_kernel<<<(NN * HH + 255) / 256, 256>>>(x, emb_w, emb_b);
    dist_kernel<<<(EE + 255) / 256, 256>>>(pos, ei);

    for (int l = 0; l < LL; l++) {
        zero_aggr_kernel<<<(NN * HH + 255) / 256, 256>>>();
        edge_kernel<<<EE / TE, 256, smem>>>(
            ei,
            msg_w1 + (size_t)l * 257 * HH, msg_b1 + (size_t)l * HH,
            msg_w2 + (size_t)l * HH * HH,  msg_b2 + (size_t)l * HH);
        node_kernel<<<(NN + TE - 1) / TE, 256, smem>>>(
            node_w1 + (size_t)l * 256 * HH, node_b1 + (size_t)l * HH,
            node_w2 + (size_t)l * HH * HH,  node_b2 + (size_t)l * HH);
    }

    zero_pool_kernel<<<(GG * HH + 255) / 256, 256>>>();
    pool_kernel<<<(NN * 32 + 255) / 256, 256>>>(batch);
    out_kernel<<<GG, 32>>>(out_w1, out_b1, out_w2, out_b2, (float*)d_out);
}

// round 8
// speedup vs baseline: 1.9078x; 1.9078x over previous
#include <cuda_runtime.h>
#include <cuda_bf16.h>
#include <mma.h>
#include <cstdint>

using namespace nvcuda;

#define NN 30000
#define EE 600000
#define HH 128
#define LL 4
#define GG 64
#define TMR 128      // rows per tile
#define LDA 136      // leading dim (elements) for bf16 planes and float stage

// ---------------- scratch (static device globals; no allocation) ----------
__device__ __align__(256) float g_h[NN * HH];
__device__ __align__(256) float g_aggr[NN * HH];
__device__ __align__(256) float g_dist[EE];
__device__ __align__(256) float g_pool[GG * HH];
__device__ int g_is64;

// ---------------- helpers ----------------
__device__ __forceinline__ int ld_idx(const void* p, long long i, int is64) {
    if (is64) return (int)((const long long*)p)[i];
    return ((const int*)p)[i];
}
__device__ __forceinline__ float silu_f(float v) {
    return v / (1.0f + __expf(-v));
}
// Two-way bf16 split via documented intrinsics only.
__device__ __forceinline__ void split_bf16(float x, __nv_bfloat16& h, __nv_bfloat16& m) {
    h = __float2bfloat16_rn(x);
    float r = x - __bfloat162float(h);
    m = __float2bfloat16_rn(r);
}

// ---------------- auxiliary kernels ----------------
__global__ void detect_kernel(const int* w) {
    __shared__ int nz;
    if (threadIdx.x == 0) nz = 0;
    __syncthreads();
    int f = 0;
    for (int i = threadIdx.x * 2 + 1; i < 4096; i += 2 * 256)
        if (w[i] != 0) f = 1;
    if (f) atomicOr(&nz, 1);
    __syncthreads();
    if (threadIdx.x == 0) g_is64 = (nz == 0) ? 1 : 0;
}

__global__ void embed_kernel(const float* __restrict__ x,
                             const float* __restrict__ w,
                             const float* __restrict__ b) {
    int idx = blockIdx.x * blockDim.x + threadIdx.x;
    if (idx >= NN * HH) return;
    int n = idx >> 7, k = idx & 127;
    g_h[idx] = x[n] * w[k] + b[k];
}

__global__ void dist_kernel(const float* __restrict__ pos, const void* ei) {
    int e = blockIdx.x * blockDim.x + threadIdx.x;
    if (e >= EE) return;
    int is64 = g_is64;
    int r = ld_idx(ei, e, is64);
    int c = ld_idx(ei, (long long)EE + e, is64);
    float dx = pos[3 * r + 0] - pos[3 * c + 0];
    float dy = pos[3 * r + 1] - pos[3 * c + 1];
    float dz = pos[3 * r + 2] - pos[3 * c + 2];
    g_dist[e] = dx * dx + dy * dy + dz * dz;
}

__global__ void zero_aggr_kernel() {
    int idx = blockIdx.x * blockDim.x + threadIdx.x;
    if (idx < NN * HH) g_aggr[idx] = 0.0f;
}
__global__ void zero_pool_kernel() {
    int idx = blockIdx.x * blockDim.x + threadIdx.x;
    if (idx < GG * HH) g_pool[idx] = 0.0f;
}

// ---------------------------------------------------------------------------
// Fused MLP layer kernel (WMMA bf16, 2-way split, 4-term products).
// mode 0 = edge layer, 1 = node layer.
// SMEM (bytes):
//   sAhi  @ 0       (128*136 bf16 = 34816)
//   sAmid @ 34816
//   sBhi  @ 69632
//   sBmid @ 104448
//   stage = float[128][136] overlays sBhi..sBmid (69632 bytes, exact fit)
//   sCol @ 139264, sRow @ 139776 ; total 140288
// ---------------------------------------------------------------------------
#define SMEM_LAYER 140288

__global__ __launch_bounds__(256) void layer_kernel(
    int mode, const void* __restrict__ ei,
    const float* __restrict__ W1, const float* __restrict__ B1,
    const float* __restrict__ W2, const float* __restrict__ B2) {
    extern __shared__ char smem[];
    __nv_bfloat16* sAhi  = (__nv_bfloat16*)smem;
    __nv_bfloat16* sAmid = sAhi + TMR * LDA;
    __nv_bfloat16* sBhi  = sAmid + TMR * LDA;
    __nv_bfloat16* sBmid = sBhi + TMR * LDA;
    float* stage = (float*)sBhi;                  // overlays both B planes
    int* sCol = (int*)(sBmid + TMR * LDA);
    int* sRow = sCol + TMR;

    const int tid = threadIdx.x, lane = tid & 31, wid = tid >> 5;
    const int wr = wid & 1, wc = wid >> 1;        // warp tile: rows wr*64, cols wc*32
    const int tile = blockIdx.x;
    const int is64 = g_is64;

    if (tid < TMR) {
        if (mode == 0) {
            long long e = (long long)tile * TMR + tid;
            long long ec = (e < EE) ? e : 0;
            sRow[tid] = ld_idx(ei, ec, is64);
            sCol[tid] = ld_idx(ei, (long long)EE + ec, is64);
        } else {
            int n = tile * TMR + tid;
            sCol[tid] = (n < NN) ? n : 0;
        }
    }
    __syncthreads();

    wmma::fragment<wmma::accumulator, 16, 16, 16, float> acc[4][2];
#pragma unroll
    for (int mt = 0; mt < 4; mt++)
#pragma unroll
        for (int nt = 0; nt < 2; nt++)
            wmma::fill_fragment(acc[mt][nt], 0.0f);

    // ================= GEMM1: K chunks of 128 =================
    for (int c = 0; c < 2; c++) {
        if (c) __syncthreads();   // previous chunk reads complete before refill

        // A chunk: gather + split. 2 threads per row, 64 floats each.
        {
            const int r = tid >> 1, half = tid & 1;
            const float* src = (mode == 0)
                ? g_h + (size_t)((c == 0) ? sCol[r] : sRow[r]) * HH
                : ((c == 0) ? g_h : g_aggr) + (size_t)sCol[r] * HH;
            const float4* s4 = (const float4*)(src + half * 64);
            __nv_bfloat16* dh = sAhi + r * LDA + half * 64;
            __nv_bfloat16* dm = sAmid + r * LDA + half * 64;
#pragma unroll
            for (int i = 0; i < 16; i++) {
                float4 v = s4[i];
                split_bf16(v.x, dh[i * 4 + 0], dm[i * 4 + 0]);
                split_bf16(v.y, dh[i * 4 + 1], dm[i * 4 + 1]);
                split_bf16(v.z, dh[i * 4 + 2], dm[i * 4 + 2]);
                split_bf16(v.w, dh[i * 4 + 3], dm[i * 4 + 3]);
            }
        }
        // B chunk: W1 rows [c*128, +128), layout [k][n] row-major.
        {
            const int k = tid >> 1, half = tid & 1;
            const float4* s4 = (const float4*)(W1 + (size_t)(c * 128 + k) * 128 + half * 64);
            __nv_bfloat16* dh = sBhi + k * LDA + half * 64;
            __nv_bfloat16* dm = sBmid + k * LDA + half * 64;
#pragma unroll
            for (int i = 0; i < 16; i++) {
                float4 v = s4[i];
                split_bf16(v.x, dh[i * 4 + 0], dm[i * 4 + 0]);
                split_bf16(v.y, dh[i * 4 + 1], dm[i * 4 + 1]);
                split_bf16(v.z, dh[i * 4 + 2], dm[i * 4 + 2]);
                split_bf16(v.w, dh[i * 4 + 3], dm[i * 4 + 3]);
            }
        }
        __syncthreads();

        for (int ks = 0; ks < 8; ks++) {
            const int k0 = ks * 16;
            wmma::fragment<wmma::matrix_b, 16, 16, 16, __nv_bfloat16, wmma::row_major> bh[2], bm[2];
#pragma unroll
            for (int nt = 0; nt < 2; nt++) {
                wmma::load_matrix_sync(bh[nt], sBhi + k0 * LDA + wc * 32 + nt * 16, LDA);
                wmma::load_matrix_sync(bm[nt], sBmid + k0 * LDA + wc * 32 + nt * 16, LDA);
            }
#pragma unroll
            for (int mt = 0; mt < 4; mt++) {
                const int r0 = wr * 64 + mt * 16;
                wmma::fragment<wmma::matrix_a, 16, 16, 16, __nv_bfloat16, wmma::row_major> ah, am;
                wmma::load_matrix_sync(ah, sAhi + r0 * LDA + k0, LDA);
                wmma::load_matrix_sync(am, sAmid + r0 * LDA + k0, LDA);
#pragma unroll
                for (int nt = 0; nt < 2; nt++) {
                    wmma::mma_sync(acc[mt][nt], ah, bh[nt], acc[mt][nt]);
                    wmma::mma_sync(acc[mt][nt], ah, bm[nt], acc[mt][nt]);
                    wmma::mma_sync(acc[mt][nt], am, bh[nt], acc[mt][nt]);
                    wmma::mma_sync(acc[mt][nt], am, bm[nt], acc[mt][nt]);
                }
            }
        }
    }
    __syncthreads();   // all GEMM1 reads of B planes done; stage may be written

    // ---- store acc1 -> stage (fp32) ----
#pragma unroll
    for (int mt = 0; mt < 4; mt++)
#pragma unroll
        for (int nt = 0; nt < 2; nt++)
            wmma::store_matrix_sync(stage + (wr * 64 + mt * 16) * LDA + wc * 32 + nt * 16,
                                    acc[mt][nt], LDA, wmma::mem_row_major);
    __syncthreads();

    // ---- epilogue 1: D1 + b1 (+ dist*W1[256]) -> silu -> split -> A planes ----
    {
        const int r = tid >> 1, half = tid & 1;
        float dv = 0.0f;
        if (mode == 0) {
            long long e = (long long)tile * TMR + r;
            dv = (e < EE) ? g_dist[e] : 0.0f;
        }
        const float* w256 = W1 + (size_t)256 * 128;   // only read in edge mode
        __nv_bfloat16* dh = sAhi + r * LDA + half * 64;
        __nv_bfloat16* dm = sAmid + r * LDA + half * 64;
        const float* st = stage + r * LDA + half * 64;
#pragma unroll
        for (int i = 0; i < 64; i++) {
            const int cc = half * 64 + i;
            float v = st[i] + B1[cc];
            if (mode == 0) v += dv * w256[cc];
            v = silu_f(v);
            split_bf16(v, dh[i], dm[i]);
        }
    }
    __syncthreads();   // stage fully read before W2 overwrites it

    // ---- load W2 -> B planes ----
    {
        const int k = tid >> 1, half = tid & 1;
        const float4* s4 = (const float4*)(W2 + (size_t)k * 128 + half * 64);
        __nv_bfloat16* dh = sBhi + k * LDA + half * 64;
        __nv_bfloat16* dm = sBmid + k * LDA + half * 64;
#pragma unroll
        for (int i = 0; i < 16; i++) {
            float4 v = s4[i];
            split_bf16(v.x, dh[i * 4 + 0], dm[i * 4 + 0]);
            split_bf16(v.y, dh[i * 4 + 1], dm[i * 4 + 1]);
            split_bf16(v.z, dh[i * 4 + 2], dm[i * 4 + 2]);
            split_bf16(v.w, dh[i * 4 + 3], dm[i * 4 + 3]);
        }
    }
    __syncthreads();

    // ================= GEMM2: K = 128 =================
#pragma unroll
    for (int mt = 0; mt < 4; mt++)
#pragma unroll
        for (int nt = 0; nt < 2; nt++)
            wmma::fill_fragment(acc[mt][nt], 0.0f);

    for (int ks = 0; ks < 8; ks++) {
        const int k0 = ks * 16;
        wmma::fragment<wmma::matrix_b, 16, 16, 16, __nv_bfloat16, wmma::row_major> bh[2], bm[2];
#pragma unroll
        for (int nt = 0; nt < 2; nt++) {
            wmma::load_matrix_sync(bh[nt], sBhi + k0 * LDA + wc * 32 + nt * 16, LDA);
            wmma::load_matrix_sync(bm[nt], sBmid + k0 * LDA + wc * 32 + nt * 16, LDA);
        }
#pragma unroll
        for (int mt = 0; mt < 4; mt++) {
            const int r0 = wr * 64 + mt * 16;
            wmma::fragment<wmma::matrix_a, 16, 16, 16, __nv_bfloat16, wmma::row_major> ah, am;
            wmma::load_matrix_sync(ah, sAhi + r0 * LDA + k0, LDA);
            wmma::load_matrix_sync(am, sAmid + r0 * LDA + k0, LDA);
#pragma unroll
            for (int nt = 0; nt < 2; nt++) {
                wmma::mma_sync(acc[mt][nt], ah, bh[nt], acc[mt][nt]);
                wmma::mma_sync(acc[mt][nt], ah, bm[nt], acc[mt][nt]);
                wmma::mma_sync(acc[mt][nt], am, bh[nt], acc[mt][nt]);
                wmma::mma_sync(acc[mt][nt], am, bm[nt], acc[mt][nt]);
            }
        }
    }
    __syncthreads();   // all GEMM2 reads of B planes done

    // ---- store acc2 -> stage ----
#pragma unroll
    for (int mt = 0; mt < 4; mt++)
#pragma unroll
        for (int nt = 0; nt < 2; nt++)
            wmma::store_matrix_sync(stage + (wr * 64 + mt * 16) * LDA + wc * 32 + nt * 16,
                                    acc[mt][nt], LDA, wmma::mem_row_major);
    __syncthreads();

    // ---- epilogue 2: + b2, output ----
    if (mode == 0) {
        for (int rr = wid; rr < TMR; rr += 8) {
            long long e = (long long)tile * TMR + rr;
            if (e < EE) {
                const float4 v = *(const float4*)(stage + rr * LDA + lane * 4);
                const float4 b = *(const float4*)(B2 + lane * 4);
                float* dst = g_aggr + (size_t)sCol[rr] * HH + lane * 4;
                asm volatile("red.global.add.v4.f32 [%0], {%1,%2,%3,%4};"
                             :: "l"(dst), "f"(v.x + b.x), "f"(v.y + b.y),
                                "f"(v.z + b.z), "f"(v.w + b.w)
                             : "memory");
            }
        }
    } else {
        for (int rr = wid; rr < TMR; rr += 8) {
            int n = tile * TMR + rr;
            if (n < NN) {
                const float4 v = *(const float4*)(stage + rr * LDA + lane * 4);
                const float4 b = *(const float4*)(B2 + lane * 4);
                *(float4*)(g_h + (size_t)n * HH + lane * 4) =
                    make_float4(v.x + b.x, v.y + b.y, v.z + b.z, v.w + b.w);
            }
        }
    }
}

// ---------------- pooling + output head ----------------
__global__ void pool_kernel(const void* batch) {
    int idx = blockIdx.x * blockDim.x + threadIdx.x;
    if (idx >= NN * 32) return;
    int n = idx >> 5, qq = idx & 31;
    int b = ld_idx(batch, n, g_is64);
    float4 v = ((const float4*)(g_h + (size_t)n * HH))[qq];
    float* dst = &g_pool[b * HH + qq * 4];
    atomicAdd(dst + 0, v.x);
    atomicAdd(dst + 1, v.y);
    atomicAdd(dst + 2, v.z);
    atomicAdd(dst + 3, v.w);
}

__global__ void out_kernel(const float* __restrict__ w1, const float* __restrict__ b1,
                           const float* __restrict__ w2, const float* __restrict__ b2,
                           float* __restrict__ out) {
    int gi = blockIdx.x;
    int j = threadIdx.x;  // 0..31
    float s = b1[j];
    for (int k = 0; k < HH; k++)
        s += g_pool[gi * HH + k] * w1[k * 32 + j];
    float v = silu_f(s) * w2[j];
#pragma unroll
    for (int o = 16; o > 0; o >>= 1)
        v += __shfl_down_sync(0xFFFFFFFFu, v, o);
    if (j == 0) out[gi] = v + b2[0];
}

extern "C" void kernel_launch(void* const* d_in, const int* in_sizes, int n_in,
                              void* d_out, int out_size) {
    const float* x       = (const float*)d_in[0];
    const float* pos     = (const float*)d_in[1];
    const void*  ei      = d_in[2];
    const void*  batch   = d_in[3];
    const float* emb_w   = (const float*)d_in[4];
    const float* emb_b   = (const float*)d_in[5];
    const float* msg_w1  = (const float*)d_in[6];
    const float* msg_b1  = (const float*)d_in[7];
    const float* msg_w2  = (const float*)d_in[8];
    const float* msg_b2  = (const float*)d_in[9];
    const float* node_w1 = (const float*)d_in[10];
    const float* node_b1 = (const float*)d_in[11];
    const float* node_w2 = (const float*)d_in[12];
    const float* node_b2 = (const float*)d_in[13];
    const float* out_w1  = (const float*)d_in[14];
    const float* out_b1  = (const float*)d_in[15];
    const float* out_w2  = (const float*)d_in[16];
    const float* out_b2  = (const float*)d_in[17];

    cudaFuncSetAttribute(layer_kernel, cudaFuncAttributeMaxDynamicSharedMemorySize,
                         SMEM_LAYER);

    detect_kernel<<<1, 256>>>((const int*)ei);
    embed_kernel<<<(NN * HH + 255) / 256, 256>>>(x, emb_w, emb_b);
    dist_kernel<<<(EE + 255) / 256, 256>>>(pos, ei);

    const int egrid = (EE + TMR - 1) / TMR;   // 4688
    const int ngrid = (NN + TMR - 1) / TMR;   // 235

    for (int l = 0; l < LL; l++) {
        zero_aggr_kernel<<<(NN * HH + 255) / 256, 256>>>();
        layer_kernel<<<egrid, 256, SMEM_LAYER>>>(
            0, ei,
            msg_w1 + (size_t)l * 257 * HH, msg_b1 + (size_t)l * HH,
            msg_w2 + (size_t)l * HH * HH,  msg_b2 + (size_t)l * HH);
        layer_kernel<<<ngrid, 256, SMEM_LAYER>>>(
            1, ei,
            node_w1 + (size_t)l * 256 * HH, node_b1 + (size_t)l * HH,
            node_w2 + (size_t)l * HH * HH,  node_b2 + (size_t)l * HH);
    }

    zero_pool_kernel<<<(GG * HH + 255) / 256, 256>>>();
    pool_kernel<<<(NN * 32 + 255) / 256, 256>>>(batch);
    out_kernel<<<GG, 32>>>(out_w1, out_b1, out_w2, out_b2, (float*)d_out);
}

// round 11
// speedup vs baseline: 2.2585x; 1.1838x over previous
#include <cuda_runtime.h>
#include <cuda_bf16.h>
#include <mma.h>
#include <cstdint>

using namespace nvcuda;

#define NN 30000
#define EE 600000
#define HH 128
#define LL 4
#define GG 64
#define TMR 128      // rows per tile
#define LDA 136      // leading dim (elements) for bf16 planes and float stage
#define WROWS 769    // per-layer pre-split weight rows: 257 + 128 + 256 + 128

// ---------------- scratch (static device globals; no allocation) ----------
__device__ __align__(256) float g_h[NN * HH];        // fp32 h (for pool)
__device__ __align__(256) __nv_bfloat16 g_hhi[NN * HH];
__device__ __align__(256) __nv_bfloat16 g_hmid[NN * HH];
__device__ __align__(256) float g_aggr[NN * HH];
__device__ __align__(256) float g_dist[EE];
__device__ __align__(256) float g_pool[GG * HH];
__device__ __align__(256) __nv_bfloat16 g_whi[LL * WROWS * HH];
__device__ __align__(256) __nv_bfloat16 g_wmid[LL * WROWS * HH];
__device__ int g_is64;

// ---------------- helpers ----------------
__device__ __forceinline__ int ld_idx(const void* p, long long i, int is64) {
    if (is64) return (int)((const long long*)p)[i];
    return ((const int*)p)[i];
}
__device__ __forceinline__ float silu_f(float v) {
    return v / (1.0f + __expf(-v));
}
__device__ __forceinline__ void split_bf16(float x, __nv_bfloat16& h, __nv_bfloat16& m) {
    h = __float2bfloat16_rn(x);
    float r = x - __bfloat162float(h);
    m = __float2bfloat16_rn(r);
}

// ---------------- auxiliary kernels ----------------
__global__ void detect_kernel(const int* w) {
    __shared__ int nz;
    if (threadIdx.x == 0) nz = 0;
    __syncthreads();
    int f = 0;
    for (int i = threadIdx.x * 2 + 1; i < 4096; i += 2 * 256)
        if (w[i] != 0) f = 1;
    if (f) atomicOr(&nz, 1);
    __syncthreads();
    if (threadIdx.x == 0) g_is64 = (nz == 0) ? 1 : 0;
}

// Pre-split all per-layer weights into bf16 hi/mid planes.
// Row layout per layer: [0,257)=msg_w1, [257,385)=msg_w2, [385,641)=node_w1, [641,769)=node_w2
__global__ void prep_w_kernel(const float* __restrict__ msg_w1,
                              const float* __restrict__ msg_w2,
                              const float* __restrict__ node_w1,
                              const float* __restrict__ node_w2) {
    int id = blockIdx.x * blockDim.x + threadIdx.x;
    if (id >= LL * WROWS * HH) return;
    int l = id / (WROWS * HH);
    int rem = id - l * (WROWS * HH);
    int row = rem >> 7, n = rem & 127;
    float v;
    if (row < 257)      v = msg_w1[((size_t)l * 257 + row) * HH + n];
    else if (row < 385) v = msg_w2[((size_t)l * 128 + (row - 257)) * HH + n];
    else if (row < 641) v = node_w1[((size_t)l * 256 + (row - 385)) * HH + n];
    else                v = node_w2[((size_t)l * 128 + (row - 641)) * HH + n];
    __nv_bfloat16 h, m;
    split_bf16(v, h, m);
    g_whi[id] = h;
    g_wmid[id] = m;
}

__global__ void embed_kernel(const float* __restrict__ x,
                             const float* __restrict__ w,
                             const float* __restrict__ b) {
    int idx = blockIdx.x * blockDim.x + threadIdx.x;
    if (idx >= NN * HH) return;
    int n = idx >> 7, k = idx & 127;
    float v = x[n] * w[k] + b[k];
    g_h[idx] = v;
    __nv_bfloat16 h, m;
    split_bf16(v, h, m);
    g_hhi[idx] = h;
    g_hmid[idx] = m;
}

__global__ void dist_kernel(const float* __restrict__ pos, const void* ei) {
    int e = blockIdx.x * blockDim.x + threadIdx.x;
    if (e >= EE) return;
    int is64 = g_is64;
    int r = ld_idx(ei, e, is64);
    int c = ld_idx(ei, (long long)EE + e, is64);
    float dx = pos[3 * r + 0] - pos[3 * c + 0];
    float dy = pos[3 * r + 1] - pos[3 * c + 1];
    float dz = pos[3 * r + 2] - pos[3 * c + 2];
    g_dist[e] = dx * dx + dy * dy + dz * dz;
}

__global__ void zero_aggr_kernel() {
    int idx = blockIdx.x * blockDim.x + threadIdx.x;
    if (idx < NN * HH) g_aggr[idx] = 0.0f;
}
__global__ void zero_pool_kernel() {
    int idx = blockIdx.x * blockDim.x + threadIdx.x;
    if (idx < GG * HH) g_pool[idx] = 0.0f;
}

// ---------------------------------------------------------------------------
// Fused MLP layer kernel (WMMA bf16, 2-way split, 3-term products).
// mode 0 = edge layer, 1 = node layer. Weight planes taken from g_whi/g_wmid
// at per-layer row offsets (w1row, w2row) computed on device.
// SMEM: sAhi | sAmid | sBhi | sBmid (each 128*136 bf16 = 34816B);
//       stage float[128][136] overlays sBhi..sBmid; sCol/sRow at end.
// ---------------------------------------------------------------------------
#define SMEM_LAYER 140288

__global__ __launch_bounds__(256) void layer_kernel(
    int mode, int layer, const void* __restrict__ ei,
    const float* __restrict__ W1f,          // fp32 msg_w1 base for this layer (dist row); null in node mode
    const float* __restrict__ B1, const float* __restrict__ B2) {
    extern __shared__ char smem[];
    __nv_bfloat16* sAhi  = (__nv_bfloat16*)smem;
    __nv_bfloat16* sAmid = sAhi + TMR * LDA;
    __nv_bfloat16* sBhi  = sAmid + TMR * LDA;
    __nv_bfloat16* sBmid = sBhi + TMR * LDA;
    float* stage = (float*)sBhi;                  // overlays both B planes
    int* sCol = (int*)(sBmid + TMR * LDA);
    int* sRow = sCol + TMR;

    // per-layer pre-split weight plane bases
    const size_t lbase = (size_t)layer * WROWS * HH;
    const __nv_bfloat16* w1hi  = g_whi  + lbase + (size_t)(mode == 0 ? 0 : 385) * HH;
    const __nv_bfloat16* w1mid = g_wmid + lbase + (size_t)(mode == 0 ? 0 : 385) * HH;
    const __nv_bfloat16* w2hi  = g_whi  + lbase + (size_t)(mode == 0 ? 257 : 641) * HH;
    const __nv_bfloat16* w2mid = g_wmid + lbase + (size_t)(mode == 0 ? 257 : 641) * HH;

    const int tid = threadIdx.x, lane = tid & 31, wid = tid >> 5;
    const int wr = wid & 1, wc = wid >> 1;        // warp tile: rows wr*64, cols wc*32
    const int tile = blockIdx.x;
    const int is64 = g_is64;

    if (tid < TMR) {
        if (mode == 0) {
            long long e = (long long)tile * TMR + tid;
            long long ec = (e < EE) ? e : 0;
            sRow[tid] = ld_idx(ei, ec, is64);
            sCol[tid] = ld_idx(ei, (long long)EE + ec, is64);
        } else {
            int n = tile * TMR + tid;
            sCol[tid] = (n < NN) ? n : 0;
        }
    }
    __syncthreads();

    wmma::fragment<wmma::accumulator, 16, 16, 16, float> acc[4][2];
#pragma unroll
    for (int mt = 0; mt < 4; mt++)
#pragma unroll
        for (int nt = 0; nt < 2; nt++)
            wmma::fill_fragment(acc[mt][nt], 0.0f);

    // ================= GEMM1: K chunks of 128 =================
    for (int c = 0; c < 2; c++) {
        if (c) __syncthreads();   // previous chunk reads complete before refill

        // ---- A chunk ----
        const int r = tid >> 1, half = tid & 1;
        if (mode == 0 || c == 0) {
            // pure bf16 copy from pre-split planes (no conversion)
            const int node = (mode == 0) ? ((c == 0) ? sCol[r] : sRow[r]) : sCol[r];
            const uint4* shi = (const uint4*)(g_hhi + (size_t)node * HH + half * 64);
            const uint4* smi = (const uint4*)(g_hmid + (size_t)node * HH + half * 64);
            uint4* dh = (uint4*)(sAhi + r * LDA + half * 64);
            uint4* dm = (uint4*)(sAmid + r * LDA + half * 64);
#pragma unroll
            for (int i = 0; i < 8; i++) { dh[i] = shi[i]; dm[i] = smi[i]; }
        } else {
            // node mode chunk 1: aggr fp32, inline split (read exactly once)
            const float4* s4 = (const float4*)(g_aggr + (size_t)sCol[r] * HH + half * 64);
            __nv_bfloat16* dh = sAhi + r * LDA + half * 64;
            __nv_bfloat16* dm = sAmid + r * LDA + half * 64;
#pragma unroll
            for (int i = 0; i < 16; i++) {
                float4 v = s4[i];
                split_bf16(v.x, dh[i * 4 + 0], dm[i * 4 + 0]);
                split_bf16(v.y, dh[i * 4 + 1], dm[i * 4 + 1]);
                split_bf16(v.z, dh[i * 4 + 2], dm[i * 4 + 2]);
                split_bf16(v.w, dh[i * 4 + 3], dm[i * 4 + 3]);
            }
        }
        // ---- B chunk: pure copy of pre-split weights ----
        {
            const int k = tid >> 1;
            const uint4* shi = (const uint4*)(w1hi + (size_t)(c * 128 + k) * HH + half * 64);
            const uint4* smi = (const uint4*)(w1mid + (size_t)(c * 128 + k) * HH + half * 64);
            uint4* dh = (uint4*)(sBhi + k * LDA + half * 64);
            uint4* dm = (uint4*)(sBmid + k * LDA + half * 64);
#pragma unroll
            for (int i = 0; i < 8; i++) { dh[i] = shi[i]; dm[i] = smi[i]; }
        }
        __syncthreads();

        for (int ks = 0; ks < 8; ks++) {
            const int k0 = ks * 16;
            wmma::fragment<wmma::matrix_b, 16, 16, 16, __nv_bfloat16, wmma::row_major> bh[2], bm[2];
#pragma unroll
            for (int nt = 0; nt < 2; nt++) {
                wmma::load_matrix_sync(bh[nt], sBhi + k0 * LDA + wc * 32 + nt * 16, LDA);
                wmma::load_matrix_sync(bm[nt], sBmid + k0 * LDA + wc * 32 + nt * 16, LDA);
            }
#pragma unroll
            for (int mt = 0; mt < 4; mt++) {
                const int r0 = wr * 64 + mt * 16;
                wmma::fragment<wmma::matrix_a, 16, 16, 16, __nv_bfloat16, wmma::row_major> ah, am;
                wmma::load_matrix_sync(ah, sAhi + r0 * LDA + k0, LDA);
                wmma::load_matrix_sync(am, sAmid + r0 * LDA + k0, LDA);
#pragma unroll
                for (int nt = 0; nt < 2; nt++) {
                    wmma::mma_sync(acc[mt][nt], ah, bh[nt], acc[mt][nt]);
                    wmma::mma_sync(acc[mt][nt], ah, bm[nt], acc[mt][nt]);
                    wmma::mma_sync(acc[mt][nt], am, bh[nt], acc[mt][nt]);
                }
            }
        }
    }
    __syncthreads();   // all GEMM1 reads of B planes done; stage may be written

    // ---- store acc1 -> stage (fp32) ----
#pragma unroll
    for (int mt = 0; mt < 4; mt++)
#pragma unroll
        for (int nt = 0; nt < 2; nt++)
            wmma::store_matrix_sync(stage + (wr * 64 + mt * 16) * LDA + wc * 32 + nt * 16,
                                    acc[mt][nt], LDA, wmma::mem_row_major);
    __syncthreads();

    // ---- epilogue 1: D1 + b1 (+ dist*W1[256]) -> silu -> split -> A planes ----
    {
        const int r = tid >> 1, half = tid & 1;
        float dv = 0.0f;
        if (mode == 0) {
            long long e = (long long)tile * TMR + r;
            dv = (e < EE) ? g_dist[e] : 0.0f;
        }
        __nv_bfloat16* dh = sAhi + r * LDA + half * 64;
        __nv_bfloat16* dm = sAmid + r * LDA + half * 64;
        const float* st = stage + r * LDA + half * 64;
#pragma unroll
        for (int i = 0; i < 64; i++) {
            const int cc = half * 64 + i;
            float v = st[i] + B1[cc];
            if (mode == 0) v += dv * W1f[(size_t)256 * 128 + cc];
            v = silu_f(v);
            split_bf16(v, dh[i], dm[i]);
        }
    }
    __syncthreads();   // stage fully read before W2 overwrites it

    // ---- load W2 -> B planes (pure copy) ----
    {
        const int k = tid >> 1, half = tid & 1;
        const uint4* shi = (const uint4*)(w2hi + (size_t)k * HH + half * 64);
        const uint4* smi = (const uint4*)(w2mid + (size_t)k * HH + half * 64);
        uint4* dh = (uint4*)(sBhi + k * LDA + half * 64);
        uint4* dm = (uint4*)(sBmid + k * LDA + half * 64);
#pragma unroll
        for (int i = 0; i < 8; i++) { dh[i] = shi[i]; dm[i] = smi[i]; }
    }
    __syncthreads();

    // ================= GEMM2: K = 128 =================
#pragma unroll
    for (int mt = 0; mt < 4; mt++)
#pragma unroll
        for (int nt = 0; nt < 2; nt++)
            wmma::fill_fragment(acc[mt][nt], 0.0f);

    for (int ks = 0; ks < 8; ks++) {
        const int k0 = ks * 16;
        wmma::fragment<wmma::matrix_b, 16, 16, 16, __nv_bfloat16, wmma::row_major> bh[2], bm[2];
#pragma unroll
        for (int nt = 0; nt < 2; nt++) {
            wmma::load_matrix_sync(bh[nt], sBhi + k0 * LDA + wc * 32 + nt * 16, LDA);
            wmma::load_matrix_sync(bm[nt], sBmid + k0 * LDA + wc * 32 + nt * 16, LDA);
        }
#pragma unroll
        for (int mt = 0; mt < 4; mt++) {
            const int r0 = wr * 64 + mt * 16;
            wmma::fragment<wmma::matrix_a, 16, 16, 16, __nv_bfloat16, wmma::row_major> ah, am;
            wmma::load_matrix_sync(ah, sAhi + r0 * LDA + k0, LDA);
            wmma::load_matrix_sync(am, sAmid + r0 * LDA + k0, LDA);
#pragma unroll
            for (int nt = 0; nt < 2; nt++) {
                wmma::mma_sync(acc[mt][nt], ah, bh[nt], acc[mt][nt]);
                wmma::mma_sync(acc[mt][nt], ah, bm[nt], acc[mt][nt]);
                wmma::mma_sync(acc[mt][nt], am, bh[nt], acc[mt][nt]);
            }
        }
    }
    __syncthreads();   // all GEMM2 reads of B planes done

    // ---- store acc2 -> stage ----
#pragma unroll
    for (int mt = 0; mt < 4; mt++)
#pragma unroll
        for (int nt = 0; nt < 2; nt++)
            wmma::store_matrix_sync(stage + (wr * 64 + mt * 16) * LDA + wc * 32 + nt * 16,
                                    acc[mt][nt], LDA, wmma::mem_row_major);
    __syncthreads();

    // ---- epilogue 2: + b2, output ----
    if (mode == 0) {
        for (int rr = wid; rr < TMR; rr += 8) {
            long long e = (long long)tile * TMR + rr;
            if (e < EE) {
                const float4 v = *(const float4*)(stage + rr * LDA + lane * 4);
                const float4 b = *(const float4*)(B2 + lane * 4);
                float* dst = g_aggr + (size_t)sCol[rr] * HH + lane * 4;
                asm volatile("red.global.add.v4.f32 [%0], {%1,%2,%3,%4};"
                             :: "l"(dst), "f"(v.x + b.x), "f"(v.y + b.y),
                                "f"(v.z + b.z), "f"(v.w + b.w)
                             : "memory");
            }
        }
    } else {
        for (int rr = wid; rr < TMR; rr += 8) {
            int n = tile * TMR + rr;
            if (n < NN) {
                const float4 v = *(const float4*)(stage + rr * LDA + lane * 4);
                const float4 b = *(const float4*)(B2 + lane * 4);
                float4 o = make_float4(v.x + b.x, v.y + b.y, v.z + b.z, v.w + b.w);
                *(float4*)(g_h + (size_t)n * HH + lane * 4) = o;
                // write pre-split planes for next layer's edge gather
                __nv_bfloat16* dh = g_hhi + (size_t)n * HH + lane * 4;
                __nv_bfloat16* dm = g_hmid + (size_t)n * HH + lane * 4;
                __nv_bfloat16 h0, m0, h1, m1, h2, m2, h3, m3;
                split_bf16(o.x, h0, m0); split_bf16(o.y, h1, m1);
                split_bf16(o.z, h2, m2); split_bf16(o.w, h3, m3);
                dh[0] = h0; dh[1] = h1; dh[2] = h2; dh[3] = h3;
                dm[0] = m0; dm[1] = m1; dm[2] = m2; dm[3] = m3;
            }
        }
    }
}

// ---------------- pooling + output head ----------------
__global__ void pool_kernel(const void* batch) {
    int idx = blockIdx.x * blockDim.x + threadIdx.x;
    if (idx >= NN * 32) return;
    int n = idx >> 5, qq = idx & 31;
    int b = ld_idx(batch, n, g_is64);
    float4 v = ((const float4*)(g_h + (size_t)n * HH))[qq];
    float* dst = &g_pool[b * HH + qq * 4];
    atomicAdd(dst + 0, v.x);
    atomicAdd(dst + 1, v.y);
    atomicAdd(dst + 2, v.z);
    atomicAdd(dst + 3, v.w);
}

__global__ void out_kernel(const float* __restrict__ w1, const float* __restrict__ b1,
                           const float* __restrict__ w2, const float* __restrict__ b2,
                           float* __restrict__ out) {
    int gi = blockIdx.x;
    int j = threadIdx.x;  // 0..31
    float s = b1[j];
    for (int k = 0; k < HH; k++)
        s += g_pool[gi * HH + k] * w1[k * 32 + j];
    float v = silu_f(s) * w2[j];
#pragma unroll
    for (int o = 16; o > 0; o >>= 1)
        v += __shfl_down_sync(0xFFFFFFFFu, v, o);
    if (j == 0) out[gi] = v + b2[0];
}

extern "C" void kernel_launch(void* const* d_in, const int* in_sizes, int n_in,
                              void* d_out, int out_size) {
    const float* x       = (const float*)d_in[0];
    const float* pos     = (const float*)d_in[1];
    const void*  ei      = d_in[2];
    const void*  batch   = d_in[3];
    const float* emb_w   = (const float*)d_in[4];
    const float* emb_b   = (const float*)d_in[5];
    const float* msg_w1  = (const float*)d_in[6];
    const float* msg_b1  = (const float*)d_in[7];
    const float* msg_w2  = (const float*)d_in[8];
    const float* msg_b2  = (const float*)d_in[9];
    const float* node_w1 = (const float*)d_in[10];
    const float* node_b1 = (const float*)d_in[11];
    const float* node_w2 = (const float*)d_in[12];
    const float* node_b2 = (const float*)d_in[13];
    const float* out_w1  = (const float*)d_in[14];
    const float* out_b1  = (const float*)d_in[15];
    const float* out_w2  = (const float*)d_in[16];
    const float* out_b2  = (const float*)d_in[17];

    cudaFuncSetAttribute(layer_kernel, cudaFuncAttributeMaxDynamicSharedMemorySize,
                         SMEM_LAYER);

    detect_kernel<<<1, 256>>>((const int*)ei);
    prep_w_kernel<<<(LL * WROWS * HH + 255) / 256, 256>>>(msg_w1, msg_w2, node_w1, node_w2);
    embed_kernel<<<(NN * HH + 255) / 256, 256>>>(x, emb_w, emb_b);
    dist_kernel<<<(EE + 255) / 256, 256>>>(pos, ei);

    const int egrid = (EE + TMR - 1) / TMR;   // 4688
    const int ngrid = (NN + TMR - 1) / TMR;   // 235

    for (int l = 0; l < LL; l++) {
        zero_aggr_kernel<<<(NN * HH + 255) / 256, 256>>>();
        layer_kernel<<<egrid, 256, SMEM_LAYER>>>(
            0, l, ei,
            msg_w1 + (size_t)l * 257 * HH,
            msg_b1 + (size_t)l * HH, msg_b2 + (size_t)l * HH);
        layer_kernel<<<ngrid, 256, SMEM_LAYER>>>(
            1, l, ei,
            nullptr,
            node_b1 + (size_t)l * HH, node_b2 + (size_t)l * HH);
    }

    zero_pool_kernel<<<(GG * HH + 255) / 256, 256>>>();
    pool_kernel<<<(NN * 32 + 255) / 256, 256>>>(batch);
    out_kernel<<<GG, 32>>>(out_w1, out_b1, out_w2, out_b2, (float*)d_out);
}